// round 6
// baseline (speedup 1.0000x reference)
#include <cuda_runtime.h>
#include <cuda_bf16.h>
#include <math.h>
#include <float.h>

// Problem shape (LG_MGC_2731599200834): B=256, L=576, D=1024, k=24
#define D_DIM   1024
#define NVEC    (D_DIM / 4)      // 256 float4 per row
#define MAX_L   576
#define MAX_K   64
#define NTHREADS 512             // 16 warps; 2 blocks/SM -> all 256 blocks in ONE wave

// ---------------------------------------------------------------------------
// Fused kernel: sims -> bottom-k select -> gather-mean, one block per batch.
//
// Ranking by dot * rsqrt(|t|^2) is order-equivalent to the reference cosine
// (n_i is a positive per-batch scalar; the eps clamp is inactive at these
// magnitudes), and only the ranking order matters for index selection.
// ---------------------------------------------------------------------------
__global__ void __launch_bounds__(NTHREADS, 2)
fused_topk_kernel(const float* __restrict__ i_feats,
                  const float* __restrict__ image_feats,
                  const int* __restrict__ k_ptr,
                  float* __restrict__ out,
                  int L)
{
    __shared__ float4 s_i[NVEC];          //  4 KB  i_feats row
    __shared__ float  s_v[MAX_L];         //  2.3KB sims
    __shared__ int    s_idx[MAX_K];       //  selected indices (by rank)
    __shared__ float4 s_part[NTHREADS];   //  8 KB  gather partials

    const int b    = blockIdx.x;
    const int tid  = threadIdx.x;
    const int warp = tid >> 5;            // 0..15
    const int lane = tid & 31;

    int k = *k_ptr;
    if (k < 1) k = 1;
    if (k > MAX_K) k = MAX_K;

    // ---- load i_feats row to smem (first 256 threads) ----
    if (tid < NVEC)
        s_i[tid] = reinterpret_cast<const float4*>(i_feats + (size_t)b * D_DIM)[tid];
    __syncthreads();

    const float4* __restrict__ rowbase = reinterpret_cast<const float4*>(
        image_feats + (size_t)b * L * D_DIM);

    // ---- phase 1: sims. warp w handles tokens w, w+16, ... (36 each) ----
    for (int t = warp; t < L; t += 16) {
        const float4* __restrict__ tok = rowbase + (size_t)t * NVEC + lane;
        float dot = 0.f, nt2 = 0.f;
        #pragma unroll
        for (int j = 0; j < NVEC / 32; ++j) {          // 8 iterations
            float4 v = __ldg(tok + j * 32);            // coalesced 128B/warp
            float4 a = s_i[lane + j * 32];
            dot += a.x * v.x + a.y * v.y + a.z * v.z + a.w * v.w;
            nt2 += v.x * v.x + v.y * v.y + v.z * v.z + v.w * v.w;
        }
        #pragma unroll
        for (int off = 16; off > 0; off >>= 1) {
            dot += __shfl_xor_sync(0xffffffffu, dot, off);
            nt2 += __shfl_xor_sync(0xffffffffu, nt2, off);
        }
        if (lane == 0)
            s_v[t] = dot * rsqrtf(fmaxf(nt2, 1e-16f));
    }
    __syncthreads();

    // ---- phase 2: parallel rank-based bottom-k.
    // rank(i) = #{ j : v_j < v_i || (v_j == v_i && j < i) }; rank < k
    // selects the k smallest with top_k-stable tie-breaking; writes are a
    // collision-free compaction into s_idx. Each thread covers tokens
    // tid and tid+512 (L=576 > 512).
    for (int i = tid; i < L; i += NTHREADS) {
        const float v = s_v[i];
        int rank = 0;
        #pragma unroll 8
        for (int j = 0; j < MAX_L; ++j) {
            float w = s_v[j];                           // LDS broadcast
            rank += (w < v) | ((w == v) & (j < i));
        }
        if (rank < k)
            s_idx[rank] = i;
    }
    __syncthreads();

    // ---- phase 3: gather-mean. 2 groups x 256 threads; group g sums
    //      tokens g, g+2, ...; thread owns one float4 slot (coalesced). ----
    const int group = tid >> 8;          // 0..1
    const int slot  = tid & (NVEC - 1);  // 0..255

    float4 acc = make_float4(0.f, 0.f, 0.f, 0.f);
    #pragma unroll 6
    for (int j = group; j < k; j += 2) {
        float4 v = __ldg(rowbase + (size_t)s_idx[j] * NVEC + slot);
        acc.x += v.x; acc.y += v.y; acc.z += v.z; acc.w += v.w;
    }
    s_part[tid] = acc;
    __syncthreads();

    if (group == 0) {
        float4 a0 = s_part[slot];
        float4 a1 = s_part[NVEC + slot];
        const float inv_k = 1.0f / (float)k;
        float4 r;
        r.x = (a0.x + a1.x) * inv_k;
        r.y = (a0.y + a1.y) * inv_k;
        r.z = (a0.z + a1.z) * inv_k;
        r.w = (a0.w + a1.w) * inv_k;
        reinterpret_cast<float4*>(out + (size_t)b * D_DIM)[slot] = r;
    }
}

// ---------------------------------------------------------------------------
extern "C" void kernel_launch(void* const* d_in, const int* in_sizes, int n_in,
                              void* d_out, int out_size)
{
    const float* i_feats     = (const float*)d_in[0];   // [B, D]
    const float* image_feats = (const float*)d_in[1];   // [B, L, D]
    const int*   k_ptr       = (const int*)d_in[2];     // scalar k

    const int B = in_sizes[0] / D_DIM;                  // 256
    const int L = in_sizes[1] / in_sizes[0];            // 576

    fused_topk_kernel<<<B, NTHREADS>>>(i_feats, image_feats, k_ptr,
                                       (float*)d_out, L);
}